// round 1
// baseline (speedup 1.0000x reference)
#include <cuda_runtime.h>
#include <cuda_bf16.h>
#include <math.h>

// ---------------- problem constants ----------------
#define Bv   4
#define Tv   1024
#define Dv   2048
#define Hv   32
#define DHv  64
#define HKv  8
#define Rv   32          // RQ == RKV
#define ROv  1024
#define RFv  1024
#define Iv   5632
#define BT   (Bv*Tv)     // 4096

// ---------------- scratch (device globals; no allocs allowed) ----------------
__device__ float g_h1 [BT*Dv];
__device__ float g_qr [BT*(Hv*Rv)];
__device__ float g_kr [BT*(HKv*Rv)];
__device__ float g_vr [BT*(HKv*Rv)];
__device__ float g_q  [Bv*Hv*Tv*DHv];
__device__ float g_k  [Bv*HKv*Tv*DHv];
__device__ float g_v  [Bv*HKv*Tv*DHv];
__device__ float g_ctx[BT*Dv];
__device__ float g_or [BT*ROv];
__device__ float g_x1 [BT*Dv];
__device__ float g_h2 [BT*Dv];
__device__ float g_gr [BT*RFv];
__device__ float g_ur [BT*RFv];
__device__ float g_g  [BT*Iv];
__device__ float g_ff [BT*Iv];
__device__ float g_dr [BT*RFv];

// ---------------- RMSNorm: one block per row, D=2048 ----------------
__global__ void __launch_bounds__(256) rms_kernel(const float* __restrict__ x,
                                                  const float* __restrict__ w,
                                                  float* __restrict__ out)
{
    int row = blockIdx.x;
    int tid = threadIdx.x;
    const float4* xr = (const float4*)(x + (size_t)row * Dv);
    float4 v0 = xr[tid];
    float4 v1 = xr[tid + 256];
    float ss = v0.x*v0.x + v0.y*v0.y + v0.z*v0.z + v0.w*v0.w
             + v1.x*v1.x + v1.y*v1.y + v1.z*v1.z + v1.w*v1.w;
    #pragma unroll
    for (int o = 16; o; o >>= 1) ss += __shfl_xor_sync(0xffffffffu, ss, o);
    __shared__ float red[8];
    if ((tid & 31) == 0) red[tid >> 5] = ss;
    __syncthreads();
    float tot = 0.f;
    #pragma unroll
    for (int i = 0; i < 8; i++) tot += red[i];
    float inv = rsqrtf(tot * (1.0f / Dv) + 1e-5f);
    const float4* wr = (const float4*)w;
    float4 w0 = wr[tid], w1 = wr[tid + 256];
    float4 o0 = { v0.x*inv*w0.x, v0.y*inv*w0.y, v0.z*inv*w0.z, v0.w*inv*w0.w };
    float4 o1 = { v1.x*inv*w1.x, v1.y*inv*w1.y, v1.z*inv*w1.z, v1.w*inv*w1.w };
    float4* orow = (float4*)(out + (size_t)row * Dv);
    orow[tid] = o0;
    orow[tid + 256] = o1;
}

// ---------------- SGEMM: C[M,N] = A[M,K] @ B[N,K]^T (+ epilogue) ----------------
// mode 0: plain; mode 1: C = acc + aux; mode 2: C = silu(aux)*acc
#define GBM 128
#define GBN 128
#define GBK 8
__global__ void __launch_bounds__(256) gemm_nt(const float* __restrict__ A,
                                               const float* __restrict__ Bw,
                                               float* __restrict__ C,
                                               int M, int N, int K,
                                               int mode, const float* __restrict__ aux)
{
    __shared__ __align__(16) float As[GBK][GBM];
    __shared__ __align__(16) float Bs[GBK][GBN];

    int tid = threadIdx.x;
    int bm = blockIdx.y * GBM;
    int bn = blockIdx.x * GBN;

    int lrow = tid >> 1;        // 0..127
    int lk   = (tid & 1) * 4;   // 0 or 4
    const float* Aptr = A  + (size_t)(bm + lrow) * K + lk;
    const float* Bptr = Bw + (size_t)(bn + lrow) * K + lk;

    float acc[8][8];
    #pragma unroll
    for (int i = 0; i < 8; i++)
        #pragma unroll
        for (int j = 0; j < 8; j++) acc[i][j] = 0.f;

    int tx = tid & 15, ty = tid >> 4;
    int ri0 = ty * 4, cj0 = tx * 4;

    for (int k0 = 0; k0 < K; k0 += GBK) {
        float4 av = *(const float4*)Aptr;
        float4 bv = *(const float4*)Bptr;
        As[lk+0][lrow] = av.x; As[lk+1][lrow] = av.y;
        As[lk+2][lrow] = av.z; As[lk+3][lrow] = av.w;
        Bs[lk+0][lrow] = bv.x; Bs[lk+1][lrow] = bv.y;
        Bs[lk+2][lrow] = bv.z; Bs[lk+3][lrow] = bv.w;
        __syncthreads();
        #pragma unroll
        for (int kk = 0; kk < GBK; kk++) {
            float4 a0 = *(const float4*)&As[kk][ri0];
            float4 a1 = *(const float4*)&As[kk][ri0 + 64];
            float4 b0 = *(const float4*)&Bs[kk][cj0];
            float4 b1 = *(const float4*)&Bs[kk][cj0 + 64];
            float a[8] = {a0.x,a0.y,a0.z,a0.w,a1.x,a1.y,a1.z,a1.w};
            float b[8] = {b0.x,b0.y,b0.z,b0.w,b1.x,b1.y,b1.z,b1.w};
            #pragma unroll
            for (int i = 0; i < 8; i++)
                #pragma unroll
                for (int j = 0; j < 8; j++)
                    acc[i][j] = fmaf(a[i], b[j], acc[i][j]);
        }
        __syncthreads();
        Aptr += GBK; Bptr += GBK;
    }

    #pragma unroll
    for (int ih = 0; ih < 2; ih++) {
        #pragma unroll
        for (int r = 0; r < 4; r++) {
            int i = ih * 4 + r;
            int row = bm + (ih ? 64 : 0) + ri0 + r;
            size_t rowoff = (size_t)row * N;
            #pragma unroll
            for (int jh = 0; jh < 2; jh++) {
                int col = bn + (jh ? 64 : 0) + cj0;
                size_t idx = rowoff + col;
                float4 o;
                o.x = acc[i][jh*4+0]; o.y = acc[i][jh*4+1];
                o.z = acc[i][jh*4+2]; o.w = acc[i][jh*4+3];
                if (mode == 1) {
                    float4 rsd = *(const float4*)(aux + idx);
                    o.x += rsd.x; o.y += rsd.y; o.z += rsd.z; o.w += rsd.w;
                } else if (mode == 2) {
                    float4 gg = *(const float4*)(aux + idx);
                    o.x *= gg.x / (1.f + expf(-gg.x));
                    o.y *= gg.y / (1.f + expf(-gg.y));
                    o.z *= gg.z / (1.f + expf(-gg.z));
                    o.w *= gg.w / (1.f + expf(-gg.w));
                }
                *(float4*)(C + idx) = o;
            }
        }
    }
}

// ---------------- per-head Us projection (+ optional RoPE) ----------------
// in:  [BT, heads*32] ; Us: [heads, 64, 32] ; out: [B, heads, T, 64]
__global__ void __launch_bounds__(256) usproj_kernel(const float* __restrict__ in,
                                                     const float* __restrict__ Us,
                                                     float* __restrict__ out,
                                                     int heads, int rope)
{
    __shared__ __align__(16) float inT[32][64];  // [r][i]
    __shared__ __align__(16) float UsT[32][64];  // [r][d]
    __shared__ __align__(16) float os [64][64];  // [i][d]
    int h = blockIdx.y;
    int bt0 = blockIdx.x * 64;
    int tid = threadIdx.x;
    int ldin = heads * 32;

    { // Us[h] : [64,32] -> UsT[r][d]
        int d = tid >> 2; int r0 = (tid & 3) * 8;
        const float* p = Us + ((size_t)h * 64 + d) * 32 + r0;
        float4 u0 = *(const float4*)p;
        float4 u1 = *(const float4*)(p + 4);
        UsT[r0+0][d]=u0.x; UsT[r0+1][d]=u0.y; UsT[r0+2][d]=u0.z; UsT[r0+3][d]=u0.w;
        UsT[r0+4][d]=u1.x; UsT[r0+5][d]=u1.y; UsT[r0+6][d]=u1.z; UsT[r0+7][d]=u1.w;
    }
    { // in tile [64,32] -> inT[r][i]
        int i = tid >> 2; int r0 = (tid & 3) * 8;
        const float* p = in + (size_t)(bt0 + i) * ldin + h * 32 + r0;
        float4 a0 = *(const float4*)p;
        float4 a1 = *(const float4*)(p + 4);
        inT[r0+0][i]=a0.x; inT[r0+1][i]=a0.y; inT[r0+2][i]=a0.z; inT[r0+3][i]=a0.w;
        inT[r0+4][i]=a1.x; inT[r0+5][i]=a1.y; inT[r0+6][i]=a1.z; inT[r0+7][i]=a1.w;
    }
    __syncthreads();

    int tx = tid & 15, ty = tid >> 4;
    float acc[4][4] = {};
    #pragma unroll
    for (int r = 0; r < 32; r++) {
        float4 a = *(const float4*)&inT[r][ty*4];
        float4 b = *(const float4*)&UsT[r][tx*4];
        float av[4] = {a.x,a.y,a.z,a.w};
        float bv[4] = {b.x,b.y,b.z,b.w};
        #pragma unroll
        for (int rr = 0; rr < 4; rr++)
            #pragma unroll
            for (int cc = 0; cc < 4; cc++)
                acc[rr][cc] = fmaf(av[rr], bv[cc], acc[rr][cc]);
    }
    #pragma unroll
    for (int rr = 0; rr < 4; rr++)
        #pragma unroll
        for (int cc = 0; cc < 4; cc++)
            os[ty*4+rr][tx*4+cc] = acc[rr][cc];
    __syncthreads();

    if (!rope) {
        #pragma unroll
        for (int kk = 0; kk < 4; kk++) {
            int lin4 = tid + kk * 256;       // over 1024 float4
            int i = lin4 >> 4; int d0 = (lin4 & 15) * 4;
            int bt = bt0 + i; int b = bt >> 10; int t = bt & 1023;
            float4 vv = *(const float4*)&os[i][d0];
            size_t addr = (((size_t)(b * heads + h)) * Tv + t) * 64 + d0;
            *(float4*)(out + addr) = vv;
        }
    } else {
        #pragma unroll
        for (int kk = 0; kk < 2; kk++) {
            int lin4 = tid + kk * 256;       // over 512 (64 rows x 8 quads of half-dim)
            int i = lin4 >> 3; int d0 = (lin4 & 7) * 4;
            int bt = bt0 + i; int b = bt >> 10; int t = bt & 1023;
            float4 x1 = *(const float4*)&os[i][d0];
            float4 x2 = *(const float4*)&os[i][d0 + 32];
            float o1[4], o2[4];
            float xx1[4] = {x1.x,x1.y,x1.z,x1.w};
            float xx2[4] = {x2.x,x2.y,x2.z,x2.w};
            #pragma unroll
            for (int c = 0; c < 4; c++) {
                int d = d0 + c;
                float invf = expf(-0.28782313662425572f * (float)d); // 10000^(-d/32)
                float ang = (float)t * invf;
                float cc = cosf(ang), ssn = sinf(ang);
                o1[c] = xx1[c] * cc - xx2[c] * ssn;
                o2[c] = xx2[c] * cc + xx1[c] * ssn;
            }
            size_t base = (((size_t)(b * heads + h)) * Tv + t) * 64;
            float4 w1 = {o1[0],o1[1],o1[2],o1[3]};
            float4 w2 = {o2[0],o2[1],o2[2],o2[3]};
            *(float4*)(out + base + d0)      = w1;
            *(float4*)(out + base + d0 + 32) = w2;
        }
    }
}

// ---------------- flash attention (causal, GQA 4:1), fp32 ----------------
// q: [B,32,T,64], k/v: [B,8,T,64]; ctx out: [BT, 2048] (= [B,T,H*DH])
__global__ void __launch_bounds__(256) attn_kernel(const float* __restrict__ q,
                                                   const float* __restrict__ k,
                                                   const float* __restrict__ v,
                                                   float* __restrict__ ctx)
{
    __shared__ __align__(16) float QsT[64][64];  // [d][i]
    __shared__ __align__(16) float KsT[64][32];  // [d][j]
    __shared__ __align__(16) float Vs [32][64];  // [j][d]
    __shared__ __align__(16) float Ss [64][33];
    __shared__ float mrow[64], lrow[64], rsrow[64];

    int tid = threadIdx.x;
    int bh = blockIdx.y; int b = bh >> 5; int h = bh & 31; int hk = h >> 2;
    int q0 = blockIdx.x * 64;

    const float* qbase = q + (((size_t)(b * 32 + h)) * Tv + q0) * 64;
    #pragma unroll
    for (int kk = 0; kk < 4; kk++) {
        int lin4 = tid + kk * 256;
        int i = lin4 >> 4; int d0 = (lin4 & 15) * 4;
        float4 qv = *(const float4*)(qbase + (size_t)i * 64 + d0);
        QsT[d0+0][i] = qv.x * 0.125f;
        QsT[d0+1][i] = qv.y * 0.125f;
        QsT[d0+2][i] = qv.z * 0.125f;
        QsT[d0+3][i] = qv.w * 0.125f;
    }
    if (tid < 64) { mrow[tid] = -INFINITY; lrow[tid] = 0.f; }

    float acc[4][4] = {};
    int tx = tid & 15, ty = tid >> 4;
    int txs = tid & 7, tys = tid >> 3;
    const float* kbase0 = k + ((size_t)(b * 8 + hk)) * Tv * 64;
    const float* vbase0 = v + ((size_t)(b * 8 + hk)) * Tv * 64;

    int ntile = (q0 >> 5) + 2;
    for (int kt = 0; kt < ntile; kt++) {
        __syncthreads();
        #pragma unroll
        for (int kk = 0; kk < 2; kk++) {
            int lin4 = tid + kk * 256;
            int j = lin4 >> 4; int d0 = (lin4 & 15) * 4;
            size_t off = ((size_t)(kt * 32 + j)) * 64 + d0;
            float4 kv = *(const float4*)(kbase0 + off);
            KsT[d0+0][j] = kv.x; KsT[d0+1][j] = kv.y;
            KsT[d0+2][j] = kv.z; KsT[d0+3][j] = kv.w;
            float4 vv = *(const float4*)(vbase0 + off);
            *(float4*)&Vs[j][d0] = vv;
        }
        __syncthreads();

        // S = Q K^T on a 64x32 tile; 2 rows x 4 cols per thread
        float s[2][4] = {};
        int i0 = tys * 2;
        #pragma unroll
        for (int d = 0; d < 64; d++) {
            float a0 = QsT[d][i0], a1 = QsT[d][i0 + 1];
            float4 bb = *(const float4*)&KsT[d][txs * 4];
            s[0][0] = fmaf(a0, bb.x, s[0][0]); s[0][1] = fmaf(a0, bb.y, s[0][1]);
            s[0][2] = fmaf(a0, bb.z, s[0][2]); s[0][3] = fmaf(a0, bb.w, s[0][3]);
            s[1][0] = fmaf(a1, bb.x, s[1][0]); s[1][1] = fmaf(a1, bb.y, s[1][1]);
            s[1][2] = fmaf(a1, bb.z, s[1][2]); s[1][3] = fmaf(a1, bb.w, s[1][3]);
        }
        #pragma unroll
        for (int r = 0; r < 2; r++)
            #pragma unroll
            for (int c = 0; c < 4; c++) {
                int qi = q0 + i0 + r, ki = kt * 32 + txs * 4 + c;
                Ss[i0 + r][txs * 4 + c] = (ki <= qi) ? s[r][c] : -INFINITY;
            }
        __syncthreads();

        if (tid < 64) {
            int row = tid;
            float mo = mrow[row], mx = mo;
            #pragma unroll 8
            for (int j = 0; j < 32; j++) mx = fmaxf(mx, Ss[row][j]);
            float rsc = expf(mo - mx);
            float sum = 0.f;
            #pragma unroll 8
            for (int j = 0; j < 32; j++) {
                float p = expf(Ss[row][j] - mx);
                Ss[row][j] = p; sum += p;
            }
            mrow[row] = mx;
            lrow[row] = lrow[row] * rsc + sum;
            rsrow[row] = rsc;
        }
        __syncthreads();

        #pragma unroll
        for (int r = 0; r < 4; r++) {
            float rr = rsrow[ty * 4 + r];
            #pragma unroll
            for (int c = 0; c < 4; c++) acc[r][c] *= rr;
        }
        #pragma unroll 4
        for (int j = 0; j < 32; j++) {
            float4 vv = *(const float4*)&Vs[j][tx * 4];
            #pragma unroll
            for (int r = 0; r < 4; r++) {
                float p = Ss[ty * 4 + r][j];
                acc[r][0] = fmaf(p, vv.x, acc[r][0]);
                acc[r][1] = fmaf(p, vv.y, acc[r][1]);
                acc[r][2] = fmaf(p, vv.z, acc[r][2]);
                acc[r][3] = fmaf(p, vv.w, acc[r][3]);
            }
        }
    }
    __syncthreads();

    #pragma unroll
    for (int r = 0; r < 4; r++) {
        int i = ty * 4 + r;
        float inv = 1.f / lrow[i];
        size_t addr = ((size_t)(b * Tv + q0 + i)) * Dv + h * 64 + tx * 4;
        float4 o = { acc[r][0]*inv, acc[r][1]*inv, acc[r][2]*inv, acc[r][3]*inv };
        *(float4*)(ctx + addr) = o;
    }
}

// ---------------- launch ----------------
extern "C" void kernel_launch(void* const* d_in, const int* in_sizes, int n_in,
                              void* d_out, int out_size)
{
    const float* x     = (const float*)d_in[0];
    const float* ln1_w = (const float*)d_in[1];
    const float* ln2_w = (const float*)d_in[2];
    const float* q_Us  = (const float*)d_in[3];
    const float* q_V   = (const float*)d_in[4];
    const float* k_Us  = (const float*)d_in[5];
    const float* k_V   = (const float*)d_in[6];
    const float* v_Us  = (const float*)d_in[7];
    const float* v_V   = (const float*)d_in[8];
    const float* o_Us  = (const float*)d_in[9];
    const float* o_V   = (const float*)d_in[10];
    const float* g_Usw = (const float*)d_in[11];
    const float* g_Vw  = (const float*)d_in[12];
    const float* u_Usw = (const float*)d_in[13];
    const float* u_Vw  = (const float*)d_in[14];
    const float* d_Usw = (const float*)d_in[15];
    const float* d_Vw  = (const float*)d_in[16];
    float* out = (float*)d_out;

    float *h1, *qr, *kr, *vr, *qb, *kb, *vb, *ctx, *orr, *x1, *h2, *gr, *ur, *gg, *ff, *dr;
    cudaGetSymbolAddress((void**)&h1,  g_h1);
    cudaGetSymbolAddress((void**)&qr,  g_qr);
    cudaGetSymbolAddress((void**)&kr,  g_kr);
    cudaGetSymbolAddress((void**)&vr,  g_vr);
    cudaGetSymbolAddress((void**)&qb,  g_q);
    cudaGetSymbolAddress((void**)&kb,  g_k);
    cudaGetSymbolAddress((void**)&vb,  g_v);
    cudaGetSymbolAddress((void**)&ctx, g_ctx);
    cudaGetSymbolAddress((void**)&orr, g_or);
    cudaGetSymbolAddress((void**)&x1,  g_x1);
    cudaGetSymbolAddress((void**)&h2,  g_h2);
    cudaGetSymbolAddress((void**)&gr,  g_gr);
    cudaGetSymbolAddress((void**)&ur,  g_ur);
    cudaGetSymbolAddress((void**)&gg,  g_g);
    cudaGetSymbolAddress((void**)&ff,  g_ff);
    cudaGetSymbolAddress((void**)&dr,  g_dr);

    dim3 blk(256);

    // 1) h1 = rms(x)
    rms_kernel<<<BT, blk>>>(x, ln1_w, h1);

    // 2-4) rank projections
    gemm_nt<<<dim3((Hv*Rv)/GBN, BT/GBM), blk>>>(h1, q_V, qr, BT, Hv*Rv, Dv, 0, nullptr);
    gemm_nt<<<dim3((HKv*Rv)/GBN, BT/GBM), blk>>>(h1, k_V, kr, BT, HKv*Rv, Dv, 0, nullptr);
    gemm_nt<<<dim3((HKv*Rv)/GBN, BT/GBM), blk>>>(h1, v_V, vr, BT, HKv*Rv, Dv, 0, nullptr);

    // 5-7) Us lift (+RoPE on q,k)
    usproj_kernel<<<dim3(BT/64, Hv),  blk>>>(qr, q_Us, qb, Hv, 1);
    usproj_kernel<<<dim3(BT/64, HKv), blk>>>(kr, k_Us, kb, HKv, 1);
    usproj_kernel<<<dim3(BT/64, HKv), blk>>>(vr, v_Us, vb, HKv, 0);

    // 8) attention -> ctx [BT, 2048]
    attn_kernel<<<dim3(Tv/64, Bv*Hv), blk>>>(qb, kb, vb, ctx);

    // 9-10) O projection + residual
    gemm_nt<<<dim3(ROv/GBN, BT/GBM), blk>>>(ctx, o_V, orr, BT, ROv, Dv, 0, nullptr);
    gemm_nt<<<dim3(Dv/GBN, BT/GBM), blk>>>(orr, o_Us, x1, BT, Dv, ROv, 1, x);

    // 11) h2 = rms(x1)
    rms_kernel<<<BT, blk>>>(x1, ln2_w, h2);

    // 12-15) MLP up: gr, ur, g, ff = silu(g)*u
    gemm_nt<<<dim3(RFv/GBN, BT/GBM), blk>>>(h2, g_Vw, gr, BT, RFv, Dv, 0, nullptr);
    gemm_nt<<<dim3(RFv/GBN, BT/GBM), blk>>>(h2, u_Vw, ur, BT, RFv, Dv, 0, nullptr);
    gemm_nt<<<dim3(Iv/GBN, BT/GBM), blk>>>(gr, g_Usw, gg, BT, Iv, RFv, 0, nullptr);
    gemm_nt<<<dim3(Iv/GBN, BT/GBM), blk>>>(ur, u_Usw, ff, BT, Iv, RFv, 2, gg);

    // 16-17) MLP down + residual -> out
    gemm_nt<<<dim3(RFv/GBN, BT/GBM), blk>>>(ff, d_Vw, dr, BT, RFv, Iv, 0, nullptr);
    gemm_nt<<<dim3(Dv/GBN, BT/GBM), blk>>>(dr, d_Usw, out, BT, Dv, RFv, 1, x1);
}

// round 2
// speedup vs baseline: 3.2628x; 3.2628x over previous
#include <cuda_runtime.h>
#include <cuda_bf16.h>
#include <math.h>

// ---------------- problem constants ----------------
#define Bv   4
#define Tv   1024
#define Dv   2048
#define Hv   32
#define DHv  64
#define HKv  8
#define Rv   32
#define ROv  1024
#define RFv  1024
#define Iv   5632
#define BT   (Bv*Tv)     // 4096

// ---------------- scratch ----------------
__device__ float g_h1 [BT*Dv];
__device__ float g_qr [BT*(Hv*Rv)];
__device__ float g_kr [BT*(HKv*Rv)];
__device__ float g_vr [BT*(HKv*Rv)];
__device__ float g_q  [Bv*Hv*Tv*DHv];
__device__ float g_k  [Bv*HKv*Tv*DHv];
__device__ float g_v  [Bv*HKv*Tv*DHv];
__device__ float g_ctx[BT*Dv];
__device__ float g_or [BT*ROv];
__device__ float g_x1 [BT*Dv];
__device__ float g_h2 [BT*Dv];
__device__ float g_gr [BT*RFv];
__device__ float g_ur [BT*RFv];
__device__ float g_g  [BT*Iv];
__device__ float g_ff [BT*Iv];
__device__ float g_dr [BT*RFv];

// ---------------- RMSNorm ----------------
__global__ void __launch_bounds__(256) rms_kernel(const float* __restrict__ x,
                                                  const float* __restrict__ w,
                                                  float* __restrict__ out)
{
    int row = blockIdx.x;
    int tid = threadIdx.x;
    const float4* xr = (const float4*)(x + (size_t)row * Dv);
    float4 v0 = xr[tid];
    float4 v1 = xr[tid + 256];
    float ss = v0.x*v0.x + v0.y*v0.y + v0.z*v0.z + v0.w*v0.w
             + v1.x*v1.x + v1.y*v1.y + v1.z*v1.z + v1.w*v1.w;
    #pragma unroll
    for (int o = 16; o; o >>= 1) ss += __shfl_xor_sync(0xffffffffu, ss, o);
    __shared__ float red[8];
    if ((tid & 31) == 0) red[tid >> 5] = ss;
    __syncthreads();
    float tot = 0.f;
    #pragma unroll
    for (int i = 0; i < 8; i++) tot += red[i];
    float inv = rsqrtf(tot * (1.0f / Dv) + 1e-5f);
    const float4* wr = (const float4*)w;
    float4 w0 = wr[tid], w1 = wr[tid + 256];
    float4 o0 = { v0.x*inv*w0.x, v0.y*inv*w0.y, v0.z*inv*w0.z, v0.w*inv*w0.w };
    float4 o1 = { v1.x*inv*w1.x, v1.y*inv*w1.y, v1.z*inv*w1.z, v1.w*inv*w1.w };
    float4* orow = (float4*)(out + (size_t)row * Dv);
    orow[tid] = o0;
    orow[tid + 256] = o1;
}

// ---------------- tf32 tensor-core GEMM: C[M,N] = A[M,K] @ B[N,K]^T ----------------
// mode 0: plain; mode 1: C = acc + aux; mode 2: C = silu(aux)*acc
#define TBM 128
#define TBN 128
#define TBK 32

#define CP_ASYNC16(dst, src) asm volatile("cp.async.cg.shared.global [%0], [%1], 16;\n" :: "r"(dst), "l"(src))
#define CP_COMMIT() asm volatile("cp.async.commit_group;\n" ::)
#define CP_WAIT(n)  asm volatile("cp.async.wait_group %0;\n" :: "n"(n))

#define MMA_TF32(d, a, b) \
    asm volatile("mma.sync.aligned.m16n8k8.row.col.f32.tf32.tf32.f32 " \
        "{%0,%1,%2,%3}, {%4,%5,%6,%7}, {%8,%9}, {%0,%1,%2,%3};" \
        : "+f"(d[0]), "+f"(d[1]), "+f"(d[2]), "+f"(d[3]) \
        : "r"(a[0]), "r"(a[1]), "r"(a[2]), "r"(a[3]), "r"(b[0]), "r"(b[1]))

__global__ void __launch_bounds__(256) gemm_tc(const float* __restrict__ A,
                                               const float* __restrict__ Bw,
                                               float* __restrict__ C,
                                               int M, int N, int K,
                                               int mode, const float* __restrict__ aux)
{
    extern __shared__ float smem[];
    // layout (floats): As stage0 [0,4096), As stage1 [4096,8192),
    //                  Bs stage0 [8192,12288), Bs stage1 [12288,16384)
    // tile row layout: row*32 + 4*((c ^ (row&7))) + j   (c = float4 group 0..7)
    unsigned sbase = (unsigned)__cvta_generic_to_shared(smem);

    int tid  = threadIdx.x;
    int bm = blockIdx.y * TBM;
    int bn = blockIdx.x * TBN;
    int lane = tid & 31, warp = tid >> 5;
    int wm = warp >> 1, wn = warp & 1;        // 4 x 2 warp grid
    int g  = lane >> 2, tig = lane & 3;

    // --- copy descriptors (4 float4 per thread per tile) ---
    unsigned dstoff[4];
    const float* srcA[4];
    const float* srcB[4];
    #pragma unroll
    for (int i = 0; i < 4; i++) {
        int lin = tid + i * 256;
        int row = lin >> 3, c = lin & 7;
        dstoff[i] = (unsigned)((row * 32 + ((c ^ (row & 7)) << 2)) * 4);  // bytes
        srcA[i] = A  + (size_t)(bm + row) * K + c * 4;
        srcB[i] = Bw + (size_t)(bn + row) * K + c * 4;
    }

    // --- fragment index bases ---
    int ar0[2], ar1[2], a7[2];
    #pragma unroll
    for (int mi = 0; mi < 2; mi++) {
        int r0 = wm * 32 + mi * 16 + g;
        ar0[mi] = r0 * 32 + tig;
        ar1[mi] = (r0 + 8) * 32 + tig;
        a7[mi]  = r0 & 7;
    }
    int bbase[8], b7[8];
    #pragma unroll
    for (int ni = 0; ni < 8; ni++) {
        int n = wn * 64 + ni * 8 + g;
        bbase[ni] = n * 32 + tig;
        b7[ni] = n & 7;
    }

    float acc[2][8][4];
    #pragma unroll
    for (int mi = 0; mi < 2; mi++)
        #pragma unroll
        for (int ni = 0; ni < 8; ni++)
            #pragma unroll
            for (int q = 0; q < 4; q++) acc[mi][ni][q] = 0.f;

    const int NT = K >> 5;

    // prologue: stage 0
    {
        unsigned da = sbase, db = sbase + 32768;
        #pragma unroll
        for (int i = 0; i < 4; i++) {
            CP_ASYNC16(da + dstoff[i], srcA[i]);
            CP_ASYNC16(db + dstoff[i], srcB[i]);
        }
        CP_COMMIT();
    }

    for (int kt = 0; kt < NT; kt++) {
        int st = kt & 1;
        if (kt + 1 < NT) {
            unsigned da = sbase + (unsigned)((st ^ 1) * 16384);
            unsigned db = sbase + 32768u + (unsigned)((st ^ 1) * 16384);
            const float* oa; const float* ob;
            #pragma unroll
            for (int i = 0; i < 4; i++) {
                oa = srcA[i] + (size_t)(kt + 1) * 32;
                ob = srcB[i] + (size_t)(kt + 1) * 32;
                CP_ASYNC16(da + dstoff[i], oa);
                CP_ASYNC16(db + dstoff[i], ob);
            }
            CP_COMMIT();
            CP_WAIT(1);
        } else {
            CP_WAIT(0);
        }
        __syncthreads();

        const unsigned* AsU = (const unsigned*)smem + st * 4096;
        const unsigned* BsU = (const unsigned*)smem + 8192 + st * 4096;

        #pragma unroll
        for (int s = 0; s < 4; s++) {
            int c0 = 2 * s, c1 = 2 * s + 1;
            unsigned af[2][4];
            #pragma unroll
            for (int mi = 0; mi < 2; mi++) {
                int o0 = (c0 ^ a7[mi]) << 2;
                int o1 = (c1 ^ a7[mi]) << 2;
                af[mi][0] = AsU[ar0[mi] + o0];
                af[mi][1] = AsU[ar1[mi] + o0];
                af[mi][2] = AsU[ar0[mi] + o1];
                af[mi][3] = AsU[ar1[mi] + o1];
            }
            unsigned bf[8][2];
            #pragma unroll
            for (int ni = 0; ni < 8; ni++) {
                bf[ni][0] = BsU[bbase[ni] + ((c0 ^ b7[ni]) << 2)];
                bf[ni][1] = BsU[bbase[ni] + ((c1 ^ b7[ni]) << 2)];
            }
            #pragma unroll
            for (int mi = 0; mi < 2; mi++)
                #pragma unroll
                for (int ni = 0; ni < 8; ni++)
                    MMA_TF32(acc[mi][ni], af[mi], bf[ni]);
        }
        __syncthreads();
    }

    // --- epilogue ---
    #pragma unroll
    for (int mi = 0; mi < 2; mi++) {
        int row0 = bm + wm * 32 + mi * 16 + g;
        #pragma unroll
        for (int half = 0; half < 2; half++) {
            int row = row0 + half * 8;
            size_t rowoff = (size_t)row * N;
            #pragma unroll
            for (int ni = 0; ni < 8; ni++) {
                int col = bn + wn * 64 + ni * 8 + 2 * tig;
                size_t idx = rowoff + col;
                float vx = acc[mi][ni][half * 2 + 0];
                float vy = acc[mi][ni][half * 2 + 1];
                if (mode == 1) {
                    float2 rsd = *(const float2*)(aux + idx);
                    vx += rsd.x; vy += rsd.y;
                } else if (mode == 2) {
                    float2 gg = *(const float2*)(aux + idx);
                    vx *= gg.x / (1.f + expf(-gg.x));
                    vy *= gg.y / (1.f + expf(-gg.y));
                }
                float2 o = { vx, vy };
                *(float2*)(C + idx) = o;
            }
        }
    }
}

// ---------------- per-head Us projection (+ optional RoPE) ----------------
__global__ void __launch_bounds__(256) usproj_kernel(const float* __restrict__ in,
                                                     const float* __restrict__ Us,
                                                     float* __restrict__ out,
                                                     int heads, int rope)
{
    __shared__ __align__(16) float inT[32][64];
    __shared__ __align__(16) float UsT[32][64];
    __shared__ __align__(16) float os [64][64];
    int h = blockIdx.y;
    int bt0 = blockIdx.x * 64;
    int tid = threadIdx.x;
    int ldin = heads * 32;

    {
        int d = tid >> 2; int r0 = (tid & 3) * 8;
        const float* p = Us + ((size_t)h * 64 + d) * 32 + r0;
        float4 u0 = *(const float4*)p;
        float4 u1 = *(const float4*)(p + 4);
        UsT[r0+0][d]=u0.x; UsT[r0+1][d]=u0.y; UsT[r0+2][d]=u0.z; UsT[r0+3][d]=u0.w;
        UsT[r0+4][d]=u1.x; UsT[r0+5][d]=u1.y; UsT[r0+6][d]=u1.z; UsT[r0+7][d]=u1.w;
    }
    {
        int i = tid >> 2; int r0 = (tid & 3) * 8;
        const float* p = in + (size_t)(bt0 + i) * ldin + h * 32 + r0;
        float4 a0 = *(const float4*)p;
        float4 a1 = *(const float4*)(p + 4);
        inT[r0+0][i]=a0.x; inT[r0+1][i]=a0.y; inT[r0+2][i]=a0.z; inT[r0+3][i]=a0.w;
        inT[r0+4][i]=a1.x; inT[r0+5][i]=a1.y; inT[r0+6][i]=a1.z; inT[r0+7][i]=a1.w;
    }
    __syncthreads();

    int tx = tid & 15, ty = tid >> 4;
    float acc[4][4] = {};
    #pragma unroll
    for (int r = 0; r < 32; r++) {
        float4 a = *(const float4*)&inT[r][ty*4];
        float4 b = *(const float4*)&UsT[r][tx*4];
        float av[4] = {a.x,a.y,a.z,a.w};
        float bv[4] = {b.x,b.y,b.z,b.w};
        #pragma unroll
        for (int rr = 0; rr < 4; rr++)
            #pragma unroll
            for (int cc = 0; cc < 4; cc++)
                acc[rr][cc] = fmaf(av[rr], bv[cc], acc[rr][cc]);
    }
    #pragma unroll
    for (int rr = 0; rr < 4; rr++)
        #pragma unroll
        for (int cc = 0; cc < 4; cc++)
            os[ty*4+rr][tx*4+cc] = acc[rr][cc];
    __syncthreads();

    if (!rope) {
        #pragma unroll
        for (int kk = 0; kk < 4; kk++) {
            int lin4 = tid + kk * 256;
            int i = lin4 >> 4; int d0 = (lin4 & 15) * 4;
            int bt = bt0 + i; int b = bt >> 10; int t = bt & 1023;
            float4 vv = *(const float4*)&os[i][d0];
            size_t addr = (((size_t)(b * heads + h)) * Tv + t) * 64 + d0;
            *(float4*)(out + addr) = vv;
        }
    } else {
        #pragma unroll
        for (int kk = 0; kk < 2; kk++) {
            int lin4 = tid + kk * 256;
            int i = lin4 >> 3; int d0 = (lin4 & 7) * 4;
            int bt = bt0 + i; int b = bt >> 10; int t = bt & 1023;
            float4 x1 = *(const float4*)&os[i][d0];
            float4 x2 = *(const float4*)&os[i][d0 + 32];
            float o1[4], o2[4];
            float xx1[4] = {x1.x,x1.y,x1.z,x1.w};
            float xx2[4] = {x2.x,x2.y,x2.z,x2.w};
            #pragma unroll
            for (int c = 0; c < 4; c++) {
                int d = d0 + c;
                float invf = expf(-0.28782313662425572f * (float)d);
                float ang = (float)t * invf;
                float cc = cosf(ang), ssn = sinf(ang);
                o1[c] = xx1[c] * cc - xx2[c] * ssn;
                o2[c] = xx2[c] * cc + xx1[c] * ssn;
            }
            size_t base = (((size_t)(b * heads + h)) * Tv + t) * 64;
            float4 w1 = {o1[0],o1[1],o1[2],o1[3]};
            float4 w2 = {o2[0],o2[1],o2[2],o2[3]};
            *(float4*)(out + base + d0)      = w1;
            *(float4*)(out + base + d0 + 32) = w2;
        }
    }
}

// ---------------- flash attention (causal, GQA 4:1), fp32 ----------------
__global__ void __launch_bounds__(256) attn_kernel(const float* __restrict__ q,
                                                   const float* __restrict__ k,
                                                   const float* __restrict__ v,
                                                   float* __restrict__ ctx)
{
    __shared__ __align__(16) float QsT[64][64];
    __shared__ __align__(16) float KsT[64][32];
    __shared__ __align__(16) float Vs [32][64];
    __shared__ __align__(16) float Ss [64][33];
    __shared__ float mrow[64], lrow[64], rsrow[64];

    int tid = threadIdx.x;
    int bh = blockIdx.y; int b = bh >> 5; int h = bh & 31; int hk = h >> 2;
    int q0 = blockIdx.x * 64;

    const float* qbase = q + (((size_t)(b * 32 + h)) * Tv + q0) * 64;
    #pragma unroll
    for (int kk = 0; kk < 4; kk++) {
        int lin4 = tid + kk * 256;
        int i = lin4 >> 4; int d0 = (lin4 & 15) * 4;
        float4 qv = *(const float4*)(qbase + (size_t)i * 64 + d0);
        QsT[d0+0][i] = qv.x * 0.125f;
        QsT[d0+1][i] = qv.y * 0.125f;
        QsT[d0+2][i] = qv.z * 0.125f;
        QsT[d0+3][i] = qv.w * 0.125f;
    }
    if (tid < 64) { mrow[tid] = -INFINITY; lrow[tid] = 0.f; }

    float acc[4][4] = {};
    int tx = tid & 15, ty = tid >> 4;
    int txs = tid & 7, tys = tid >> 3;
    const float* kbase0 = k + ((size_t)(b * 8 + hk)) * Tv * 64;
    const float* vbase0 = v + ((size_t)(b * 8 + hk)) * Tv * 64;

    int ntile = (q0 >> 5) + 2;
    for (int kt = 0; kt < ntile; kt++) {
        __syncthreads();
        #pragma unroll
        for (int kk = 0; kk < 2; kk++) {
            int lin4 = tid + kk * 256;
            int j = lin4 >> 4; int d0 = (lin4 & 15) * 4;
            size_t off = ((size_t)(kt * 32 + j)) * 64 + d0;
            float4 kv = *(const float4*)(kbase0 + off);
            KsT[d0+0][j] = kv.x; KsT[d0+1][j] = kv.y;
            KsT[d0+2][j] = kv.z; KsT[d0+3][j] = kv.w;
            float4 vv = *(const float4*)(vbase0 + off);
            *(float4*)&Vs[j][d0] = vv;
        }
        __syncthreads();

        float s[2][4] = {};
        int i0 = tys * 2;
        #pragma unroll
        for (int d = 0; d < 64; d++) {
            float a0 = QsT[d][i0], a1 = QsT[d][i0 + 1];
            float4 bb = *(const float4*)&KsT[d][txs * 4];
            s[0][0] = fmaf(a0, bb.x, s[0][0]); s[0][1] = fmaf(a0, bb.y, s[0][1]);
            s[0][2] = fmaf(a0, bb.z, s[0][2]); s[0][3] = fmaf(a0, bb.w, s[0][3]);
            s[1][0] = fmaf(a1, bb.x, s[1][0]); s[1][1] = fmaf(a1, bb.y, s[1][1]);
            s[1][2] = fmaf(a1, bb.z, s[1][2]); s[1][3] = fmaf(a1, bb.w, s[1][3]);
        }
        #pragma unroll
        for (int r = 0; r < 2; r++)
            #pragma unroll
            for (int c = 0; c < 4; c++) {
                int qi = q0 + i0 + r, ki = kt * 32 + txs * 4 + c;
                Ss[i0 + r][txs * 4 + c] = (ki <= qi) ? s[r][c] : -INFINITY;
            }
        __syncthreads();

        if (tid < 64) {
            int row = tid;
            float mo = mrow[row], mx = mo;
            #pragma unroll 8
            for (int j = 0; j < 32; j++) mx = fmaxf(mx, Ss[row][j]);
            float rsc = expf(mo - mx);
            float sum = 0.f;
            #pragma unroll 8
            for (int j = 0; j < 32; j++) {
                float p = expf(Ss[row][j] - mx);
                Ss[row][j] = p; sum += p;
            }
            mrow[row] = mx;
            lrow[row] = lrow[row] * rsc + sum;
            rsrow[row] = rsc;
        }
        __syncthreads();

        #pragma unroll
        for (int r = 0; r < 4; r++) {
            float rr = rsrow[ty * 4 + r];
            #pragma unroll
            for (int c = 0; c < 4; c++) acc[r][c] *= rr;
        }
        #pragma unroll 4
        for (int j = 0; j < 32; j++) {
            float4 vv = *(const float4*)&Vs[j][tx * 4];
            #pragma unroll
            for (int r = 0; r < 4; r++) {
                float p = Ss[ty * 4 + r][j];
                acc[r][0] = fmaf(p, vv.x, acc[r][0]);
                acc[r][1] = fmaf(p, vv.y, acc[r][1]);
                acc[r][2] = fmaf(p, vv.z, acc[r][2]);
                acc[r][3] = fmaf(p, vv.w, acc[r][3]);
            }
        }
    }
    __syncthreads();

    #pragma unroll
    for (int r = 0; r < 4; r++) {
        int i = ty * 4 + r;
        float inv = 1.f / lrow[i];
        size_t addr = ((size_t)(b * Tv + q0 + i)) * Dv + h * 64 + tx * 4;
        float4 o = { acc[r][0]*inv, acc[r][1]*inv, acc[r][2]*inv, acc[r][3]*inv };
        *(float4*)(ctx + addr) = o;
    }
}

// ---------------- launch ----------------
extern "C" void kernel_launch(void* const* d_in, const int* in_sizes, int n_in,
                              void* d_out, int out_size)
{
    const float* x     = (const float*)d_in[0];
    const float* ln1_w = (const float*)d_in[1];
    const float* ln2_w = (const float*)d_in[2];
    const float* q_Us  = (const float*)d_in[3];
    const float* q_V   = (const float*)d_in[4];
    const float* k_Us  = (const float*)d_in[5];
    const float* k_V   = (const float*)d_in[6];
    const float* v_Us  = (const float*)d_in[7];
    const float* v_V   = (const float*)d_in[8];
    const float* o_Us  = (const float*)d_in[9];
    const float* o_V   = (const float*)d_in[10];
    const float* g_Usw = (const float*)d_in[11];
    const float* g_Vw  = (const float*)d_in[12];
    const float* u_Usw = (const float*)d_in[13];
    const float* u_Vw  = (const float*)d_in[14];
    const float* d_Usw = (const float*)d_in[15];
    const float* d_Vw  = (const float*)d_in[16];
    float* out = (float*)d_out;

    float *h1, *qr, *kr, *vr, *qb, *kb, *vb, *ctx, *orr, *x1, *h2, *gr, *ur, *gg, *ff, *dr;
    cudaGetSymbolAddress((void**)&h1,  g_h1);
    cudaGetSymbolAddress((void**)&qr,  g_qr);
    cudaGetSymbolAddress((void**)&kr,  g_kr);
    cudaGetSymbolAddress((void**)&vr,  g_vr);
    cudaGetSymbolAddress((void**)&qb,  g_q);
    cudaGetSymbolAddress((void**)&kb,  g_k);
    cudaGetSymbolAddress((void**)&vb,  g_v);
    cudaGetSymbolAddress((void**)&ctx, g_ctx);
    cudaGetSymbolAddress((void**)&orr, g_or);
    cudaGetSymbolAddress((void**)&x1,  g_x1);
    cudaGetSymbolAddress((void**)&h2,  g_h2);
    cudaGetSymbolAddress((void**)&gr,  g_gr);
    cudaGetSymbolAddress((void**)&ur,  g_ur);
    cudaGetSymbolAddress((void**)&gg,  g_g);
    cudaGetSymbolAddress((void**)&ff,  g_ff);
    cudaGetSymbolAddress((void**)&dr,  g_dr);

    static int smem_set = 0;
    if (!smem_set) {
        cudaFuncSetAttribute(gemm_tc, cudaFuncAttributeMaxDynamicSharedMemorySize, 65536);
        smem_set = 1;
    }
    const int SM = 65536;

    dim3 blk(256);

    rms_kernel<<<BT, blk>>>(x, ln1_w, h1);

    gemm_tc<<<dim3((Hv*Rv)/TBN, BT/TBM), blk, SM>>>(h1, q_V, qr, BT, Hv*Rv, Dv, 0, nullptr);
    gemm_tc<<<dim3((HKv*Rv)/TBN, BT/TBM), blk, SM>>>(h1, k_V, kr, BT, HKv*Rv, Dv, 0, nullptr);
    gemm_tc<<<dim3((HKv*Rv)/TBN, BT/TBM), blk, SM>>>(h1, v_V, vr, BT, HKv*Rv, Dv, 0, nullptr);

    usproj_kernel<<<dim3(BT/64, Hv),  blk>>>(qr, q_Us, qb, Hv, 1);
    usproj_kernel<<<dim3(BT/64, HKv), blk>>>(kr, k_Us, kb, HKv, 1);
    usproj_kernel<<<dim3(BT/64, HKv), blk>>>(vr, v_Us, vb, HKv, 0);

    attn_kernel<<<dim3(Tv/64, Bv*Hv), blk>>>(qb, kb, vb, ctx);

    gemm_tc<<<dim3(ROv/TBN, BT/TBM), blk, SM>>>(ctx, o_V, orr, BT, ROv, Dv, 0, nullptr);
    gemm_tc<<<dim3(Dv/TBN, BT/TBM), blk, SM>>>(orr, o_Us, x1, BT, Dv, ROv, 1, x);

    rms_kernel<<<BT, blk>>>(x1, ln2_w, h2);

    gemm_tc<<<dim3(RFv/TBN, BT/TBM), blk, SM>>>(h2, g_Vw, gr, BT, RFv, Dv, 0, nullptr);
    gemm_tc<<<dim3(RFv/TBN, BT/TBM), blk, SM>>>(h2, u_Vw, ur, BT, RFv, Dv, 0, nullptr);
    gemm_tc<<<dim3(Iv/TBN, BT/TBM), blk, SM>>>(gr, g_Usw, gg, BT, Iv, RFv, 0, nullptr);
    gemm_tc<<<dim3(Iv/TBN, BT/TBM), blk, SM>>>(ur, u_Usw, ff, BT, Iv, RFv, 2, gg);

    gemm_tc<<<dim3(RFv/TBN, BT/TBM), blk, SM>>>(ff, d_Vw, dr, BT, RFv, Iv, 0, nullptr);
    gemm_tc<<<dim3(Dv/TBN, BT/TBM), blk, SM>>>(dr, d_Usw, out, BT, Dv, RFv, 1, x1);
}